// round 1
// baseline (speedup 1.0000x reference)
#include <cuda_runtime.h>
#include <cstdint>

#define N0 6912      // 48*48*3
#define N1 27648     // 96*96*3
#define N2 110592    // 192*192*3
#define N_TOTAL (N0 + N1 + N2)   // 145152

#define NMS_CTAS 148
#define NMS_TPB  1024
#define MAX_BOXES 100
#define NEG (-1e9f)

// ---------------- scratch (device globals; no allocation) ----------------
__device__ float4 g_box[N_TOTAL];
__device__ float  g_conf[N_TOTAL];
__device__ float  g_cls[N_TOTAL];
__device__ unsigned g_encmax, g_encmin;
__device__ unsigned long long g_best[128];
__device__ unsigned g_bar_count;
__device__ unsigned g_bar_gen;

// order-preserving float <-> uint32 encoding
__device__ __forceinline__ unsigned fenc(float f) {
    unsigned u = __float_as_uint(f);
    return (u & 0x80000000u) ? ~u : (u | 0x80000000u);
}
__device__ __forceinline__ float fdec(unsigned k) {
    unsigned u = (k & 0x80000000u) ? (k & 0x7FFFFFFFu) : ~k;
    return __uint_as_float(u);
}

// ---------------- init ----------------
__global__ void init_kernel() {
    int t = threadIdx.x;
    if (t == 0) {
        g_encmax = 0u;
        g_encmin = 0xFFFFFFFFu;
        g_bar_count = 0u;
    }
    if (t < 128) g_best[t] = 0ull;
}

// ---------------- decode ----------------
__global__ void decode_kernel(const float* __restrict__ g0,
                              const float* __restrict__ g1,
                              const float* __restrict__ g2,
                              const float* __restrict__ anch) {
    int i = blockIdx.x * blockDim.x + threadIdx.x;
    float mpmax = -1e30f;
    float mpmin = 1e30f;

    if (i < N_TOTAL) {
        const float* g;
        int H, arow, local;
        if (i < N0)            { g = g0; H = 48;  arow = 2; local = i; }
        else if (i < N0 + N1)  { g = g1; H = 96;  arow = 1; local = i - N0; }
        else                   { g = g2; H = 192; arow = 0; local = i - N0 - N1; }

        int a    = local % 3;
        int cell = local / 3;
        int w    = cell % H;   // W == H for all levels
        int h    = cell / H;

        const float* p = g + (size_t)local * 85;
        float tx = p[0], ty = p[1], tw = p[2], th = p[3], obj = p[4];

        float fH = (float)H;
        float fx = (tx + (float)w) / fH;   // gsize = [H, W], last dim [x, y]
        float fy = (ty + (float)h) / fH;

        float ax = anch[arow * 6 + a * 2 + 0];
        float ay = anch[arow * 6 + a * 2 + 1];
        float bw = expf(tw) * ax;
        float bh = expf(th) * ay;

        float4 b = make_float4(fx - bw * 0.5f, fy - bh * 0.5f,
                               fx + bw * 0.5f, fy + bh * 0.5f);
        g_box[i]  = b;
        g_conf[i] = obj;

        // class argmax (first index wins ties -> strict '>' keeps first)
        float best = p[5];
        int bidx = 0;
        #pragma unroll
        for (int c = 1; c < 80; c++) {
            float v = p[5 + c];
            if (v > best) { best = v; bidx = c; }
        }
        g_cls[i] = (float)bidx;
        mpmax = best;
        mpmin = best;
    }

    // block reduce max/min of maxprob, then 2 atomics per CTA
    __shared__ float s_mx[8], s_mn[8];
    #pragma unroll
    for (int o = 16; o; o >>= 1) {
        mpmax = fmaxf(mpmax, __shfl_down_sync(0xffffffffu, mpmax, o));
        mpmin = fminf(mpmin, __shfl_down_sync(0xffffffffu, mpmin, o));
    }
    int lane = threadIdx.x & 31, warp = threadIdx.x >> 5;
    if (lane == 0) { s_mx[warp] = mpmax; s_mn[warp] = mpmin; }
    __syncthreads();
    if (threadIdx.x == 0) {
        float mx = s_mx[0], mn = s_mn[0];
        int nwarp = (blockDim.x + 31) >> 5;
        for (int k = 1; k < nwarp; k++) {
            mx = fmaxf(mx, s_mx[k]);
            mn = fminf(mn, s_mn[k]);
        }
        atomicMax(&g_encmax, fenc(mx));
        atomicMin(&g_encmin, fenc(mn));
    }
}

// ---------------- grid barrier ----------------
__device__ __forceinline__ void grid_sync() {
    __syncthreads();
    if (threadIdx.x == 0) {
        unsigned gen = atomicAdd(&g_bar_gen, 0u);  // snapshot
        __threadfence();
        unsigned t = atomicAdd(&g_bar_count, 1u);
        if (t == gridDim.x - 1) {
            g_bar_count = 0u;
            __threadfence();
            atomicExch(&g_bar_gen, gen + 1u);
        } else {
            while (atomicAdd(&g_bar_gen, 0u) == gen) {
                __nanosleep(64);
            }
        }
        __threadfence();
    }
    __syncthreads();
}

// ---------------- persistent NMS ----------------
__global__ void __launch_bounds__(NMS_TPB, 1) nms_kernel(float* __restrict__ out) {
    const int tid = threadIdx.x;
    const int gid = blockIdx.x * NMS_TPB + tid;
    const bool own = gid < N_TOTAL;

    float x1 = 0.f, y1 = 0.f, x2 = 0.f, y2 = 0.f, area = 0.f, sw = -1e30f;
    if (own) {
        float4 b = g_box[gid];
        x1 = b.x; y1 = b.y; x2 = b.z; y2 = b.w;
        area = (x2 - x1) * (y2 - y1);
        float Mx = fdec(g_encmax);
        float Mn = fdec(g_encmin);
        float c = g_conf[gid];
        sw = fmaxf(c * Mx, c * Mn);   // scores[i] = max(conf*Mmax, conf*Mmin)
    }

    __shared__ unsigned long long s_red[32];
    int nvalid = 0;

    for (int t = 0; t < MAX_BOXES; t++) {
        // packed candidate: high 32 = enc(score), low 32 = ~idx (ties -> lowest idx)
        unsigned long long cand = own
            ? (((unsigned long long)fenc(sw) << 32) | (unsigned long long)(0xFFFFFFFFu - (unsigned)gid))
            : 0ull;
        #pragma unroll
        for (int o = 16; o; o >>= 1) {
            unsigned long long v = __shfl_down_sync(0xffffffffu, cand, o);
            if (v > cand) cand = v;
        }
        if ((tid & 31) == 0) s_red[tid >> 5] = cand;
        __syncthreads();
        if (tid < 32) {
            unsigned long long v = s_red[tid];
            #pragma unroll
            for (int o = 16; o; o >>= 1) {
                unsigned long long u = __shfl_down_sync(0xffffffffu, v, o);
                if (u > v) v = u;
            }
            if (tid == 0) atomicMax(&g_best[t], v);
        }

        grid_sync();

        unsigned long long best = __ldcg(&g_best[t]);
        unsigned bkey = (unsigned)(best >> 32);
        if (bkey <= 0x80000000u) break;   // best score <= 0: all remaining invalid
        nvalid++;

        unsigned j = 0xFFFFFFFFu - (unsigned)(best & 0xFFFFFFFFull);

        if (gid == (int)j) {
            out[t * 4 + 0] = x1;
            out[t * 4 + 1] = y1;
            out[t * 4 + 2] = x2;
            out[t * 4 + 3] = y2;
            out[400 + t]   = fdec(bkey);
            out[500 + t]   = g_cls[gid];
        }

        // broadcast read of winner box, suppress by IoU (winner suppresses itself)
        float4 bj = g_box[j];
        if (own) {
            float iw = fmaxf(fminf(x2, bj.z) - fmaxf(x1, bj.x), 0.0f);
            float ih = fmaxf(fminf(y2, bj.w) - fmaxf(y1, bj.y), 0.0f);
            float inter = iw * ih;
            float aj = (bj.z - bj.x) * (bj.w - bj.y);
            float iou = inter / (area + aj - inter);
            if (iou > 0.5f) sw = NEG;
        }
        // s_red reuse is safe: next write is after grid_sync's __syncthreads
    }

    if (blockIdx.x == 0 && tid == 0) {
        out[600] = (float)nvalid;
        for (int tt = nvalid; tt < MAX_BOXES; tt++) {
            out[tt * 4 + 0] = 0.f;
            out[tt * 4 + 1] = 0.f;
            out[tt * 4 + 2] = 0.f;
            out[tt * 4 + 3] = 0.f;
            out[400 + tt]   = 0.f;
            out[500 + tt]   = 0.f;
        }
    }
}

extern "C" void kernel_launch(void* const* d_in, const int* in_sizes, int n_in,
                              void* d_out, int out_size) {
    const float* g0   = (const float*)d_in[0];
    const float* g1   = (const float*)d_in[1];
    const float* g2   = (const float*)d_in[2];
    const float* anch = (const float*)d_in[3];
    float* out = (float*)d_out;

    init_kernel<<<1, 128>>>();
    decode_kernel<<<(N_TOTAL + 255) / 256, 256>>>(g0, g1, g2, anch);
    nms_kernel<<<NMS_CTAS, NMS_TPB>>>(out);
}

// round 2
// speedup vs baseline: 2.3495x; 2.3495x over previous
#include <cuda_runtime.h>
#include <cstdint>

#define N0 6912      // 48*48*3
#define N1 27648     // 96*96*3
#define N2 110592    // 192*192*3
#define N_TOTAL 145152
#define MAX_BOXES 100

#define NBINS 4096
#define BIN_SHIFT 20
#define POSBIN0 2048          // bin of enc(+0.0) = 0x80000000 >> 20
#define CAP 4096
#define TARGET 1024

// ---------------- scratch (device globals; no allocation) ----------------
__device__ float4 g_box[N_TOTAL];
__device__ float  g_conf[N_TOTAL];
__device__ float  g_cls[N_TOTAL];
__device__ unsigned g_senc[N_TOTAL];
__device__ unsigned g_encmax, g_encmin;
__device__ unsigned g_hist[NBINS];
__device__ unsigned g_threshB;
__device__ unsigned g_ncand;
__device__ unsigned long long g_cand[CAP];

// order-preserving float <-> uint32 encoding
__device__ __forceinline__ unsigned fenc(float f) {
    unsigned u = __float_as_uint(f);
    return (u & 0x80000000u) ? ~u : (u | 0x80000000u);
}
__device__ __forceinline__ float fdec(unsigned k) {
    unsigned u = (k & 0x80000000u) ? (k & 0x7FFFFFFFu) : ~k;
    return __uint_as_float(u);
}

// ---------------- init (reset all mutable state every call) ----------------
__global__ void k_init() {
    int i = blockIdx.x * blockDim.x + threadIdx.x;
    if (i < NBINS) g_hist[i] = 0u;
    if (i == 0) {
        g_encmax = 0u;
        g_encmin = 0xFFFFFFFFu;
        g_ncand  = 0u;
        g_threshB = POSBIN0;
    }
}

// ---------------- decode: one warp per box, coalesced loads ----------------
__global__ void __launch_bounds__(1024, 1) k_decode(const float* __restrict__ g0,
                                                    const float* __restrict__ g1,
                                                    const float* __restrict__ g2,
                                                    const float* __restrict__ anch) {
    const int warp = blockIdx.x * 32 + (threadIdx.x >> 5);   // == box index, exact grid
    const int lane = threadIdx.x & 31;

    const float* g;
    int H, arow, local;
    if (warp < N0)           { g = g0; H = 48;  arow = 2; local = warp; }
    else if (warp < N0 + N1) { g = g1; H = 96;  arow = 1; local = warp - N0; }
    else                     { g = g2; H = 192; arow = 0; local = warp - N0 - N1; }

    const float* p = g + (size_t)local * 85;
    float v0 = p[lane];
    float v1 = p[32 + lane];
    float v2 = (lane < 21) ? p[64 + lane] : -3.4e38f;

    // per-lane class argmax candidates (strict > keeps lowest class on ties)
    float bv = -3.4e38f; int bc = 0x7FFFFFFF;
    if (lane >= 5)          { bv = v0; bc = lane - 5; }
    if (v1 > bv)            { bv = v1; bc = 27 + lane; }
    if (lane < 21 && v2 > bv) { bv = v2; bc = 59 + lane; }

    // warp argmax (all lanes get result), ties -> lowest class idx
    #pragma unroll
    for (int o = 16; o; o >>= 1) {
        float ov = __shfl_xor_sync(0xffffffffu, bv, o);
        int   oc = __shfl_xor_sync(0xffffffffu, bc, o);
        if (ov > bv || (ov == bv && oc < bc)) { bv = ov; bc = oc; }
    }

    float tx  = __shfl_sync(0xffffffffu, v0, 0);
    float ty  = __shfl_sync(0xffffffffu, v0, 1);
    float tw  = __shfl_sync(0xffffffffu, v0, 2);
    float th  = __shfl_sync(0xffffffffu, v0, 3);
    float obj = __shfl_sync(0xffffffffu, v0, 4);

    if (lane == 0) {
        int a    = local % 3;
        int cell = local / 3;
        int w    = cell % H;   // W == H for all levels
        int h    = cell / H;

        float fH = (float)H;
        float fx = (tx + (float)w) / fH;
        float fy = (ty + (float)h) / fH;

        float ax = anch[arow * 6 + a * 2 + 0];
        float ay = anch[arow * 6 + a * 2 + 1];
        float bw = expf(tw) * ax;
        float bh = expf(th) * ay;

        g_box[warp]  = make_float4(fx - bw * 0.5f, fy - bh * 0.5f,
                                   fx + bw * 0.5f, fy + bh * 0.5f);
        g_conf[warp] = obj;
        g_cls[warp]  = (float)bc;
    }

    // block reduce of maxprob max/min, then 2 atomics per CTA
    __shared__ float s_mx[32], s_mn[32];
    if (lane == 0) { s_mx[threadIdx.x >> 5] = bv; s_mn[threadIdx.x >> 5] = bv; }
    __syncthreads();
    if (threadIdx.x == 0) {
        float mx = s_mx[0], mn = s_mn[0];
        #pragma unroll
        for (int k = 1; k < 32; k++) {
            mx = fmaxf(mx, s_mx[k]);
            mn = fminf(mn, s_mn[k]);
        }
        atomicMax(&g_encmax, fenc(mx));
        atomicMin(&g_encmin, fenc(mn));
    }
}

// ---------------- score + histogram ----------------
__global__ void __launch_bounds__(1024, 1) k_hist() {
    __shared__ unsigned sh[NBINS];
    for (int i = threadIdx.x; i < NBINS; i += 1024) sh[i] = 0u;
    __syncthreads();

    float Mx = fdec(g_encmax);
    float Mn = fdec(g_encmin);
    for (int i = blockIdx.x * 1024 + threadIdx.x; i < N_TOTAL; i += gridDim.x * 1024) {
        float c = g_conf[i];
        float s = fmaxf(c * Mx, c * Mn);
        unsigned e = fenc(s);
        g_senc[i] = e;
        atomicAdd(&sh[e >> BIN_SHIFT], 1u);
    }
    __syncthreads();
    for (int i = threadIdx.x; i < NBINS; i += 1024) {
        unsigned v = sh[i];
        if (v) atomicAdd(&g_hist[i], v);
    }
}

// ---------------- find threshold bin (TARGET-th largest positive score) ----
__global__ void __launch_bounds__(1024, 1) k_thresh() {
    __shared__ unsigned s[1024];
    int t = threadIdx.x;
    int base = t * 4;
    unsigned cnt[4];
    unsigned csum = 0;
    #pragma unroll
    for (int k = 0; k < 4; k++) {
        int b = base + k;
        unsigned v = (b >= POSBIN0) ? g_hist[b] : 0u;
        cnt[k] = v;
        csum += v;
    }
    s[t] = csum;
    __syncthreads();
    // inclusive suffix scan over chunk sums
    for (int off = 1; off < 1024; off <<= 1) {
        unsigned v = (t + off < 1024) ? s[t + off] : 0u;
        __syncthreads();
        s[t] += v;
        __syncthreads();
    }
    unsigned sufAfter = (t < 1023) ? s[t + 1] : 0u;
    unsigned sufInc   = s[t];
    if (t == 0 && s[0] < TARGET) g_threshB = POSBIN0;   // all positives qualify
    if (sufAfter < TARGET && sufInc >= TARGET) {
        unsigned acc = sufAfter;
        int B = POSBIN0;
        for (int k = 3; k >= 0; k--) {
            acc += cnt[k];
            if (acc >= TARGET) { B = base + k; break; }
        }
        g_threshB = (unsigned)B;
    }
}

// ---------------- compact candidates above threshold ----------------
__global__ void k_compact() {
    int i = blockIdx.x * 1024 + threadIdx.x;
    if (i >= N_TOTAL) return;
    unsigned e = g_senc[i];
    if ((e >> BIN_SHIFT) >= g_threshB) {
        unsigned pos = atomicAdd(&g_ncand, 1u);
        if (pos < CAP)
            g_cand[pos] = ((unsigned long long)e << 32) |
                          (unsigned long long)(0xFFFFFFFFu - (unsigned)i);
    }
}

// ---------------- single-block sort + greedy NMS + output ----------------
__global__ void __launch_bounds__(1024, 1) k_nms(float* __restrict__ out) {
    __shared__ unsigned long long keys[CAP];   // 32 KB
    __shared__ float4 cb;
    const int t = threadIdx.x;

    unsigned M = min(g_ncand, (unsigned)CAP);
    for (int i = t; i < CAP; i += 1024)
        keys[i] = (i < (int)M) ? g_cand[i] : 0ull;
    __syncthreads();

    // bitonic sort, descending
    for (unsigned k = 2; k <= CAP; k <<= 1) {
        for (unsigned j = k >> 1; j > 0; j >>= 1) {
            for (unsigned i = t; i < CAP; i += 1024) {
                unsigned ixj = i ^ j;
                if (ixj > i) {
                    unsigned long long a = keys[i], b = keys[ixj];
                    bool desc = ((i & k) == 0);
                    if ((a < b) == desc) { keys[i] = b; keys[ixj] = a; }
                }
            }
            __syncthreads();
        }
    }

    // greedy scan: thread t holds kept[t]'s box in registers
    float kx1 = 0.f, ky1 = 0.f, kx2 = 0.f, ky2 = 0.f, karea = 0.f;
    int kept = 0;
    for (unsigned r = 0; r < M && kept < MAX_BOXES; r++) {
        unsigned long long key = keys[r];
        unsigned senc = (unsigned)(key >> 32);
        if (senc <= 0x80000000u) break;           // best score <= 0: stop
        unsigned idx = 0xFFFFFFFFu - (unsigned)(key & 0xFFFFFFFFull);

        if (t == 0) cb = g_box[idx];
        __syncthreads();

        float4 c = cb;
        float carea = (c.z - c.x) * (c.w - c.y);
        bool conflict = false;
        if (t < kept) {
            float iw = fmaxf(fminf(kx2, c.z) - fmaxf(kx1, c.x), 0.0f);
            float ih = fmaxf(fminf(ky2, c.w) - fmaxf(ky1, c.y), 0.0f);
            float inter = iw * ih;
            float iou = inter / (carea + karea - inter);
            conflict = iou > 0.5f;
        }
        if (!__syncthreads_or((int)conflict)) {
            if (t == kept) { kx1 = c.x; ky1 = c.y; kx2 = c.z; ky2 = c.w; karea = carea; }
            if (t == 0) {
                out[kept * 4 + 0] = c.x;
                out[kept * 4 + 1] = c.y;
                out[kept * 4 + 2] = c.z;
                out[kept * 4 + 3] = c.w;
                out[400 + kept]   = fdec(senc);
                out[500 + kept]   = g_cls[idx];
            }
            kept++;
        }
        __syncthreads();   // protect cb before next round's write
    }

    // zero remaining slots + num_valid
    for (int s2 = kept + t; s2 < MAX_BOXES; s2 += 1024) {
        out[s2 * 4 + 0] = 0.f;
        out[s2 * 4 + 1] = 0.f;
        out[s2 * 4 + 2] = 0.f;
        out[s2 * 4 + 3] = 0.f;
        out[400 + s2]   = 0.f;
        out[500 + s2]   = 0.f;
    }
    if (t == 0) out[600] = (float)kept;
}

extern "C" void kernel_launch(void* const* d_in, const int* in_sizes, int n_in,
                              void* d_out, int out_size) {
    const float* g0   = (const float*)d_in[0];
    const float* g1   = (const float*)d_in[1];
    const float* g2   = (const float*)d_in[2];
    const float* anch = (const float*)d_in[3];
    float* out = (float*)d_out;

    k_init<<<(NBINS + 1023) / 1024, 1024>>>();
    k_decode<<<N_TOTAL / 32, 1024>>>(g0, g1, g2, anch);   // 4536 blocks, 1 warp/box
    k_hist<<<148, 1024>>>();
    k_thresh<<<1, 1024>>>();
    k_compact<<<(N_TOTAL + 1023) / 1024, 1024>>>();
    k_nms<<<1, 1024>>>(out);
}

// round 3
// speedup vs baseline: 3.2370x; 1.3777x over previous
#include <cuda_runtime.h>
#include <cstdint>

#define N0 6912      // 48*48*3
#define N1 27648     // 96*96*3
#define N2 110592    // 192*192*3
#define N_TOTAL 145152
#define MAX_BOXES 100

#define NBINS 4096
#define BIN_SHIFT 20
#define POSBIN0 2048          // bin of enc(+0.0)
#define CAP 2048
#define PRE 1024
#define TARGET 1024
#define HIST_BLOCKS 148

// ---------------- scratch (device globals; no allocation) ----------------
__device__ float4 g_box[N_TOTAL];
__device__ float  g_conf[N_TOTAL];
__device__ float  g_cls[N_TOTAL];
__device__ unsigned g_encmax, g_encmin;
__device__ unsigned g_hist[NBINS];
__device__ unsigned g_threshB;
__device__ unsigned g_ncand;
__device__ unsigned g_done;
__device__ unsigned long long g_cand[CAP];

// order-preserving float <-> uint32 encoding
__device__ __forceinline__ unsigned fenc(float f) {
    unsigned u = __float_as_uint(f);
    return (u & 0x80000000u) ? ~u : (u | 0x80000000u);
}
__device__ __forceinline__ float fdec(unsigned k) {
    unsigned u = (k & 0x80000000u) ? (k & 0x7FFFFFFFu) : ~k;
    return __uint_as_float(u);
}

// ---------------- init ----------------
__global__ void k_init() {
    int t = threadIdx.x;
    #pragma unroll
    for (int k = 0; k < 4; k++) g_hist[t + k * 1024] = 0u;
    if (t == 0) {
        g_encmax = 0u;
        g_encmin = 0xFFFFFFFFu;
        g_ncand  = 0u;
        g_done   = 0u;
        g_threshB = POSBIN0;
    }
}

// ---------------- decode: one warp per box, coalesced loads ----------------
__global__ void __launch_bounds__(1024, 1) k_decode(const float* __restrict__ g0,
                                                    const float* __restrict__ g1,
                                                    const float* __restrict__ g2,
                                                    const float* __restrict__ anch) {
    const int warp = blockIdx.x * 32 + (threadIdx.x >> 5);   // == box index (grid exact)
    const int lane = threadIdx.x & 31;

    const float* g;
    int H, arow, local;
    if (warp < N0)           { g = g0; H = 48;  arow = 2; local = warp; }
    else if (warp < N0 + N1) { g = g1; H = 96;  arow = 1; local = warp - N0; }
    else                     { g = g2; H = 192; arow = 0; local = warp - N0 - N1; }

    const float* p = g + (size_t)local * 85;
    float v0 = p[lane];
    float v1 = p[32 + lane];
    float v2 = (lane < 21) ? p[64 + lane] : -3.4e38f;

    // per-lane class argmax candidates (ties -> lowest class)
    float bv = -3.4e38f; int bc = 0x7FFFFFFF;
    if (lane >= 5)            { bv = v0; bc = lane - 5; }
    if (v1 > bv)              { bv = v1; bc = 27 + lane; }
    if (lane < 21 && v2 > bv) { bv = v2; bc = 59 + lane; }

    #pragma unroll
    for (int o = 16; o; o >>= 1) {
        float ov = __shfl_xor_sync(0xffffffffu, bv, o);
        int   oc = __shfl_xor_sync(0xffffffffu, bc, o);
        if (ov > bv || (ov == bv && oc < bc)) { bv = ov; bc = oc; }
    }

    float tx  = __shfl_sync(0xffffffffu, v0, 0);
    float ty  = __shfl_sync(0xffffffffu, v0, 1);
    float tw  = __shfl_sync(0xffffffffu, v0, 2);
    float th  = __shfl_sync(0xffffffffu, v0, 3);
    float obj = __shfl_sync(0xffffffffu, v0, 4);

    if (lane == 0) {
        int a    = local % 3;
        int cell = local / 3;
        int w    = cell % H;   // W == H for all levels
        int h    = cell / H;

        float fH = (float)H;
        float fx = (tx + (float)w) / fH;
        float fy = (ty + (float)h) / fH;

        float ax = anch[arow * 6 + a * 2 + 0];
        float ay = anch[arow * 6 + a * 2 + 1];
        float bw = expf(tw) * ax;
        float bh = expf(th) * ay;

        g_box[warp]  = make_float4(fx - bw * 0.5f, fy - bh * 0.5f,
                                   fx + bw * 0.5f, fy + bh * 0.5f);
        g_conf[warp] = obj;
        g_cls[warp]  = (float)bc;
    }

    // block reduce of maxprob max/min, then 2 atomics per CTA
    __shared__ float s_mx[32], s_mn[32];
    if (lane == 0) { s_mx[threadIdx.x >> 5] = bv; s_mn[threadIdx.x >> 5] = bv; }
    __syncthreads();
    if (threadIdx.x == 0) {
        float mx = s_mx[0], mn = s_mn[0];
        #pragma unroll
        for (int k = 1; k < 32; k++) {
            mx = fmaxf(mx, s_mx[k]);
            mn = fminf(mn, s_mn[k]);
        }
        atomicMax(&g_encmax, fenc(mx));
        atomicMin(&g_encmin, fenc(mn));
    }
}

// ---------------- score histogram + (last block) threshold scan -----------
__global__ void __launch_bounds__(1024, 1) k_hist() {
    __shared__ unsigned sh[NBINS];
    for (int i = threadIdx.x; i < NBINS; i += 1024) sh[i] = 0u;
    __syncthreads();

    float Mx = fdec(g_encmax);
    float Mn = fdec(g_encmin);
    for (int i = blockIdx.x * 1024 + threadIdx.x; i < N_TOTAL; i += HIST_BLOCKS * 1024) {
        float c = g_conf[i];
        float s = fmaxf(c * Mx, c * Mn);
        atomicAdd(&sh[fenc(s) >> BIN_SHIFT], 1u);
    }
    __syncthreads();
    for (int i = threadIdx.x; i < NBINS; i += 1024) {
        unsigned v = sh[i];
        if (v) atomicAdd(&g_hist[i], v);
    }

    // last-block ticket: do threshold selection right here
    __shared__ unsigned s_last;
    __threadfence();
    __syncthreads();
    if (threadIdx.x == 0) s_last = atomicAdd(&g_done, 1u);
    __syncthreads();
    if (s_last != HIST_BLOCKS - 1) return;

    // this block: find smallest bin B (>= POSBIN0) with count(bins >= B) >= TARGET
    __shared__ unsigned ss[1024];
    const int t = threadIdx.x;
    unsigned c0 = __ldcg(&g_hist[POSBIN0 + 2 * t]);
    unsigned c1 = __ldcg(&g_hist[POSBIN0 + 2 * t + 1]);
    ss[t] = c0 + c1;
    __syncthreads();
    // inclusive suffix scan over 1024 chunks
    for (int off = 1; off < 1024; off <<= 1) {
        unsigned v = (t + off < 1024) ? ss[t + off] : 0u;
        __syncthreads();
        ss[t] += v;
        __syncthreads();
    }
    unsigned sufInc   = ss[t];
    unsigned sufAfter = (t < 1023) ? ss[t + 1] : 0u;
    if (t == 0 && ss[0] < TARGET) g_threshB = POSBIN0;   // all positives qualify
    if (sufAfter < TARGET && sufInc >= TARGET) {
        g_threshB = (sufAfter + c1 >= TARGET) ? (POSBIN0 + 2 * t + 1)
                                              : (POSBIN0 + 2 * t);
    }
}

// ---------------- compact candidates above threshold ----------------
__global__ void k_compact() {
    int i = blockIdx.x * 1024 + threadIdx.x;
    if (i >= N_TOTAL) return;
    float Mx = fdec(g_encmax);
    float Mn = fdec(g_encmin);
    float c = g_conf[i];
    unsigned e = fenc(fmaxf(c * Mx, c * Mn));
    if ((e >> BIN_SHIFT) >= g_threshB) {
        unsigned pos = atomicAdd(&g_ncand, 1u);
        if (pos < CAP)
            g_cand[pos] = ((unsigned long long)e << 32) |
                          (unsigned long long)(0xFFFFFFFFu - (unsigned)i);
    }
}

// ---------------- single-block: sort + prefetch + warp-greedy -------------
__global__ void __launch_bounds__(1024, 1) k_nms(float* __restrict__ out) {
    __shared__ unsigned long long keys[CAP];   // 16 KB
    __shared__ float4 sbox[PRE];               // 16 KB
    __shared__ float  scls[PRE];               // 4 KB
    const int t = threadIdx.x;

    const unsigned M = min(g_ncand, (unsigned)CAP);
    #pragma unroll
    for (int k = 0; k < CAP / 1024; k++) {
        int i = t + k * 1024;
        keys[i] = (i < (int)M) ? g_cand[i] : 0ull;
    }
    __syncthreads();

    // bitonic sort (descending), 2048 keys, 1024 comparators per pass
    for (unsigned k = 2; k <= CAP; k <<= 1) {
        for (unsigned j = k >> 1; j > 0; j >>= 1) {
            #pragma unroll
            for (unsigned b = 0; b < CAP / 1024; b++) {
                unsigned i = t + b * 1024;
                unsigned ixj = i ^ j;
                if (ixj > i) {
                    unsigned long long a = keys[i], bb = keys[ixj];
                    bool desc = ((i & k) == 0);
                    if ((a < bb) == desc) { keys[i] = bb; keys[ixj] = a; }
                }
            }
            __syncthreads();
        }
    }

    // prefetch top PRE candidates' boxes/classes into smem; zero the output
    if (t < PRE && t < (int)M) {
        unsigned idx = 0xFFFFFFFFu - (unsigned)(keys[t] & 0xFFFFFFFFull);
        sbox[t] = g_box[idx];
        scls[t] = g_cls[idx];
    }
    if (t < 601) out[t] = 0.0f;
    __syncthreads();

    // warp 0: greedy scan, kept boxes in registers (4 slots/lane = 128 cap)
    if (t < 32) {
        const int lane = t;
        float kx1[4], ky1[4], kx2[4], ky2[4], ka[4];
        int kept = 0;

        for (unsigned r = 0; r < M && kept < MAX_BOXES; r++) {
            unsigned long long key = keys[r];
            unsigned senc = (unsigned)(key >> 32);
            if (senc <= 0x80000000u) break;       // best remaining score <= 0

            float4 c;
            float cls;
            if (r < PRE) { c = sbox[r]; cls = scls[r]; }
            else {
                unsigned idx = 0xFFFFFFFFu - (unsigned)(key & 0xFFFFFFFFull);
                c = g_box[idx]; cls = g_cls[idx];
            }
            float carea = (c.z - c.x) * (c.w - c.y);

            bool conflict = false;
            #pragma unroll
            for (int q = 0; q < 4; q++) {
                if (q * 32 + lane < kept) {
                    float iw = fmaxf(fminf(kx2[q], c.z) - fmaxf(kx1[q], c.x), 0.0f);
                    float ih = fmaxf(fminf(ky2[q], c.w) - fmaxf(ky1[q], c.y), 0.0f);
                    float inter = iw * ih;
                    float iou = inter / (carea + ka[q] - inter);
                    conflict |= (iou > 0.5f);
                }
            }
            if (__ballot_sync(0xffffffffu, conflict) == 0u) {
                int s = kept;
                #pragma unroll
                for (int q = 0; q < 4; q++) {
                    if ((s >> 5) == q && lane == (s & 31)) {
                        kx1[q] = c.x; ky1[q] = c.y;
                        kx2[q] = c.z; ky2[q] = c.w;
                        ka[q]  = carea;
                    }
                }
                if (lane == 0) {
                    out[s * 4 + 0] = c.x;
                    out[s * 4 + 1] = c.y;
                    out[s * 4 + 2] = c.z;
                    out[s * 4 + 3] = c.w;
                    out[400 + s]   = fdec(senc);
                    out[500 + s]   = cls;
                }
                kept++;
            }
        }
        if (lane == 0) out[600] = (float)kept;
    }
}

extern "C" void kernel_launch(void* const* d_in, const int* in_sizes, int n_in,
                              void* d_out, int out_size) {
    const float* g0   = (const float*)d_in[0];
    const float* g1   = (const float*)d_in[1];
    const float* g2   = (const float*)d_in[2];
    const float* anch = (const float*)d_in[3];
    float* out = (float*)d_out;

    k_init<<<1, 1024>>>();
    k_decode<<<N_TOTAL / 32, 1024>>>(g0, g1, g2, anch);   // 4536 blocks, 1 warp/box
    k_hist<<<HIST_BLOCKS, 1024>>>();
    k_compact<<<(N_TOTAL + 1023) / 1024, 1024>>>();
    k_nms<<<1, 1024>>>(out);
}

// round 4
// speedup vs baseline: 3.4393x; 1.0625x over previous
#include <cuda_runtime.h>
#include <cstdint>

#define N0 6912      // 48*48*3
#define N1 27648     // 96*96*3
#define N2 110592    // 192*192*3
#define N_TOTAL 145152
#define MAX_BOXES 100

#define NBINS 4096
#define BIN_SHIFT 20
#define POSBIN0 2048          // bin of enc(+0.0)
#define CAP 2048
#define PRE 1024
#define TARGET 1024
#define FB 142                // fused-kernel blocks (142*1024 = 145408 >= N_TOTAL)

// ---------------- scratch (device globals; zero/const static init) -------
__device__ float4 g_box[N_TOTAL];
__device__ float  g_conf[N_TOTAL];
__device__ float  g_cls[N_TOTAL];
__device__ unsigned g_encmax = 0u;
__device__ unsigned g_encmin = 0xFFFFFFFFu;
__device__ unsigned g_hist[NBINS];          // zero-init
__device__ unsigned g_ncand;                // zero-init
__device__ unsigned g_bar1;                 // zero-init
__device__ unsigned g_bar2;                 // zero-init
__device__ unsigned long long g_cand[CAP];

// order-preserving float <-> uint32 encoding
__device__ __forceinline__ unsigned fenc(float f) {
    unsigned u = __float_as_uint(f);
    return (u & 0x80000000u) ? ~u : (u | 0x80000000u);
}
__device__ __forceinline__ float fdec(unsigned k) {
    unsigned u = (k & 0x80000000u) ? (k & 0x7FFFFFFFu) : ~k;
    return __uint_as_float(u);
}

// ---------------- decode: one warp per box, coalesced loads ----------------
__global__ void __launch_bounds__(1024, 1) k_decode(const float* __restrict__ g0,
                                                    const float* __restrict__ g1,
                                                    const float* __restrict__ g2,
                                                    const float* __restrict__ anch) {
    const int warp = blockIdx.x * 32 + (threadIdx.x >> 5);   // == box index (grid exact)
    const int lane = threadIdx.x & 31;

    const float* g;
    int H, arow, local;
    if (warp < N0)           { g = g0; H = 48;  arow = 2; local = warp; }
    else if (warp < N0 + N1) { g = g1; H = 96;  arow = 1; local = warp - N0; }
    else                     { g = g2; H = 192; arow = 0; local = warp - N0 - N1; }

    const float* p = g + (size_t)local * 85;
    float v0 = p[lane];
    float v1 = p[32 + lane];
    float v2 = (lane < 21) ? p[64 + lane] : -3.4e38f;

    // per-lane class argmax candidates (ties -> lowest class)
    float bv = -3.4e38f; int bc = 0x7FFFFFFF;
    if (lane >= 5)            { bv = v0; bc = lane - 5; }
    if (v1 > bv)              { bv = v1; bc = 27 + lane; }
    if (lane < 21 && v2 > bv) { bv = v2; bc = 59 + lane; }

    #pragma unroll
    for (int o = 16; o; o >>= 1) {
        float ov = __shfl_xor_sync(0xffffffffu, bv, o);
        int   oc = __shfl_xor_sync(0xffffffffu, bc, o);
        if (ov > bv || (ov == bv && oc < bc)) { bv = ov; bc = oc; }
    }

    float tx  = __shfl_sync(0xffffffffu, v0, 0);
    float ty  = __shfl_sync(0xffffffffu, v0, 1);
    float tw  = __shfl_sync(0xffffffffu, v0, 2);
    float th  = __shfl_sync(0xffffffffu, v0, 3);
    float obj = __shfl_sync(0xffffffffu, v0, 4);

    if (lane == 0) {
        int a    = local % 3;
        int cell = local / 3;
        int w    = cell % H;   // W == H for all levels
        int h    = cell / H;

        float fH = (float)H;
        float fx = (tx + (float)w) / fH;
        float fy = (ty + (float)h) / fH;

        float ax = anch[arow * 6 + a * 2 + 0];
        float ay = anch[arow * 6 + a * 2 + 1];
        float bw = expf(tw) * ax;
        float bh = expf(th) * ay;

        g_box[warp]  = make_float4(fx - bw * 0.5f, fy - bh * 0.5f,
                                   fx + bw * 0.5f, fy + bh * 0.5f);
        g_conf[warp] = obj;
        g_cls[warp]  = (float)bc;
    }

    __shared__ float s_mx[32], s_mn[32];
    if (lane == 0) { s_mx[threadIdx.x >> 5] = bv; s_mn[threadIdx.x >> 5] = bv; }
    __syncthreads();
    if (threadIdx.x == 0) {
        float mx = s_mx[0], mn = s_mn[0];
        #pragma unroll
        for (int k = 1; k < 32; k++) {
            mx = fmaxf(mx, s_mx[k]);
            mn = fminf(mn, s_mn[k]);
        }
        atomicMax(&g_encmax, fenc(mx));
        atomicMin(&g_encmin, fenc(mn));
    }
}

// register compare-exchange step for bitonic (j <= 16, via shuffle)
__device__ __forceinline__ unsigned long long cas_reg(unsigned long long v,
                                                      unsigned i, unsigned j,
                                                      unsigned k) {
    unsigned long long pv = __shfl_xor_sync(0xffffffffu, v, j);
    bool lower = (i & j) == 0u;
    bool desc  = (i & k) == 0u;
    unsigned long long mx = v > pv ? v : pv;
    unsigned long long mn = v > pv ? pv : v;
    return (lower == desc) ? mx : mn;
}

// ------- fused: hist + threshold + compact + sort + greedy NMS + reset -----
__global__ void __launch_bounds__(1024, 1) k_fused(float* __restrict__ out) {
    __shared__ __align__(16) char smem_raw[36864];   // 36 KB union
    const int t  = threadIdx.x;
    const int gi = blockIdx.x * 1024 + t;
    const bool own = gi < N_TOTAL;

    // ---- phase 1: per-thread score ----
    unsigned e = 0u;
    if (own) {
        float Mx = fdec(g_encmax);
        float Mn = fdec(g_encmin);
        float c = g_conf[gi];
        e = fenc(fmaxf(c * Mx, c * Mn));
    }

    // ---- phase 2: histogram ----
    unsigned* sh = (unsigned*)smem_raw;   // 16 KB
    #pragma unroll
    for (int k = 0; k < 4; k++) sh[t + k * 1024] = 0u;
    __syncthreads();
    if (own) atomicAdd(&sh[e >> BIN_SHIFT], 1u);
    __syncthreads();
    #pragma unroll
    for (int k = 0; k < 4; k++) {
        unsigned v = sh[t + k * 1024];
        if (v) atomicAdd(&g_hist[t + k * 1024], v);
    }

    // ---- grid barrier 1 (all blocks wait; all FB blocks co-resident) ----
    __syncthreads();
    if (t == 0) {
        __threadfence();
        atomicAdd(&g_bar1, 1u);
        while (atomicAdd(&g_bar1, 0u) < FB) __nanosleep(32);
    }
    __syncthreads();

    // ---- phase 3: every block computes threshold bin locally ----
    unsigned* ss = (unsigned*)smem_raw;   // reuse (4 KB)
    __shared__ unsigned s_thresh;
    unsigned c0 = __ldcg(&g_hist[POSBIN0 + 2 * t]);
    unsigned c1 = __ldcg(&g_hist[POSBIN0 + 2 * t + 1]);
    if (t == 0) s_thresh = POSBIN0;       // default: all positives qualify
    ss[t] = c0 + c1;
    __syncthreads();
    for (int off = 1; off < 1024; off <<= 1) {
        unsigned v = (t + off < 1024) ? ss[t + off] : 0u;
        __syncthreads();
        ss[t] += v;
        __syncthreads();
    }
    unsigned sufInc   = ss[t];
    unsigned sufAfter = (t < 1023) ? ss[t + 1] : 0u;
    if (sufAfter < TARGET && sufInc >= TARGET) {
        s_thresh = (sufAfter + c1 >= TARGET) ? (POSBIN0 + 2 * t + 1)
                                             : (POSBIN0 + 2 * t);
    }
    __syncthreads();
    const unsigned threshB = s_thresh;

    // ---- phase 4: compact ----
    if (own && (e >> BIN_SHIFT) >= threshB) {
        unsigned pos = atomicAdd(&g_ncand, 1u);
        if (pos < CAP)
            g_cand[pos] = ((unsigned long long)e << 32) |
                          (unsigned long long)(0xFFFFFFFFu - (unsigned)gi);
    }

    // ---- barrier 2: arrive-only; block 0 waits ----
    __syncthreads();
    if (t == 0) {
        __threadfence();
        atomicAdd(&g_bar2, 1u);
    }
    if (blockIdx.x != 0) return;
    if (t == 0) {
        while (atomicAdd(&g_bar2, 0u) < FB) __nanosleep(32);
    }
    __syncthreads();

    // ---- phase 5 (block 0): hybrid bitonic sort of CAP keys, descending ----
    unsigned long long* keys = (unsigned long long*)smem_raw;      // 16 KB
    float4* sbox = (float4*)(smem_raw + 16384);                    // 16 KB
    float*  scls = (float*)(smem_raw + 32768);                     // 4 KB

    const unsigned M = min(__ldcg(&g_ncand), (unsigned)CAP);
    unsigned long long a = (t        < (int)M) ? __ldcg(&g_cand[t])        : 0ull;
    unsigned long long b = (t + 1024 < (int)M) ? __ldcg(&g_cand[t + 1024]) : 0ull;

    // stages k=2..32 fully in registers
    #pragma unroll
    for (unsigned k = 2; k <= 32; k <<= 1) {
        #pragma unroll
        for (unsigned j = k >> 1; j > 0; j >>= 1) {
            a = cas_reg(a, (unsigned)t, j, k);
            b = cas_reg(b, (unsigned)t + 1024u, j, k);
        }
    }
    keys[t] = a; keys[t + 1024] = b;
    __syncthreads();

    // stages k=64..2048: j>=32 in smem, j<=16 in registers
    for (unsigned k = 64; k <= CAP; k <<= 1) {
        for (unsigned j = k >> 1; j >= 32; j >>= 1) {
            #pragma unroll
            for (unsigned bb = 0; bb < 2; bb++) {
                unsigned i = (unsigned)t + bb * 1024u;
                unsigned ixj = i ^ j;
                if (ixj > i) {
                    unsigned long long x = keys[i], y = keys[ixj];
                    bool desc = ((i & k) == 0u);
                    if ((x < y) == desc) { keys[i] = y; keys[ixj] = x; }
                }
            }
            __syncthreads();
        }
        a = keys[t]; b = keys[t + 1024];
        #pragma unroll
        for (unsigned j = 16; j > 0; j >>= 1) {
            a = cas_reg(a, (unsigned)t, j, k);
            b = cas_reg(b, (unsigned)t + 1024u, j, k);
        }
        keys[t] = a; keys[t + 1024] = b;
        __syncthreads();
    }

    // ---- phase 6: prefetch top PRE boxes; zero output ----
    if (t < PRE && t < (int)M) {
        unsigned idx = 0xFFFFFFFFu - (unsigned)(keys[t] & 0xFFFFFFFFull);
        sbox[t] = g_box[idx];
        scls[t] = g_cls[idx];
    }
    if (t < 601) out[t] = 0.0f;
    __syncthreads();

    // ---- phase 7: warp 0 greedy scan, kept boxes in registers ----
    if (t < 32) {
        const int lane = t;
        float kx1[4], ky1[4], kx2[4], ky2[4], ka[4];
        int kept = 0;

        for (unsigned r = 0; r < M && kept < MAX_BOXES; r++) {
            unsigned long long key = keys[r];
            unsigned senc = (unsigned)(key >> 32);
            if (senc <= 0x80000000u) break;       // best remaining score <= 0

            float4 c;
            float cls;
            if (r < PRE) { c = sbox[r]; cls = scls[r]; }
            else {
                unsigned idx = 0xFFFFFFFFu - (unsigned)(key & 0xFFFFFFFFull);
                c = g_box[idx]; cls = g_cls[idx];
            }
            float carea = (c.z - c.x) * (c.w - c.y);

            bool conflict = false;
            #pragma unroll
            for (int q = 0; q < 4; q++) {
                if (q * 32 + lane < kept) {
                    float iw = fmaxf(fminf(kx2[q], c.z) - fmaxf(kx1[q], c.x), 0.0f);
                    float ih = fmaxf(fminf(ky2[q], c.w) - fmaxf(ky1[q], c.y), 0.0f);
                    float inter = iw * ih;
                    float iou = inter / (carea + ka[q] - inter);
                    conflict |= (iou > 0.5f);
                }
            }
            if (__ballot_sync(0xffffffffu, conflict) == 0u) {
                int s = kept;
                #pragma unroll
                for (int q = 0; q < 4; q++) {
                    if ((s >> 5) == q && lane == (s & 31)) {
                        kx1[q] = c.x; ky1[q] = c.y;
                        kx2[q] = c.z; ky2[q] = c.w;
                        ka[q]  = carea;
                    }
                }
                if (lane == 0) {
                    out[s * 4 + 0] = c.x;
                    out[s * 4 + 1] = c.y;
                    out[s * 4 + 2] = c.z;
                    out[s * 4 + 3] = c.w;
                    out[400 + s]   = fdec(senc);
                    out[500 + s]   = cls;
                }
                kept++;
            }
        }
        if (lane == 0) out[600] = (float)kept;
    }

    // ---- phase 8: reset all mutable state for the next call ----
    __syncthreads();
    #pragma unroll
    for (int k = 0; k < 4; k++) g_hist[t + k * 1024] = 0u;
    if (t == 0) {
        g_ncand  = 0u;
        g_bar1   = 0u;
        g_bar2   = 0u;
        g_encmax = 0u;
        g_encmin = 0xFFFFFFFFu;
    }
}

extern "C" void kernel_launch(void* const* d_in, const int* in_sizes, int n_in,
                              void* d_out, int out_size) {
    const float* g0   = (const float*)d_in[0];
    const float* g1   = (const float*)d_in[1];
    const float* g2   = (const float*)d_in[2];
    const float* anch = (const float*)d_in[3];
    float* out = (float*)d_out;

    k_decode<<<N_TOTAL / 32, 1024>>>(g0, g1, g2, anch);   // 4536 blocks, 1 warp/box
    k_fused<<<FB, 1024>>>(out);
}

// round 5
// speedup vs baseline: 3.6180x; 1.0519x over previous
#include <cuda_runtime.h>
#include <cstdint>

#define N0 6912      // 48*48*3
#define N1 27648     // 96*96*3
#define N2 110592    // 192*192*3
#define N_TOTAL 145152
#define MAX_BOXES 100

#define NBINS 4096
#define BIN_SHIFT 20
#define POSBIN0 2048          // bin of enc(+0.0)
#define CAP 2048
#define PRE 1024
#define TARGET 1024
#define FB 142                // blocks (142*1024 = 145408 >= N_TOTAL)

// ---------------- scratch (device globals; zero/const static init) -------
__device__ float4 g_box[N_TOTAL];
__device__ float  g_cls[N_TOTAL];
__device__ unsigned g_encmax = 0u;
__device__ unsigned g_encmin = 0xFFFFFFFFu;
__device__ unsigned g_hist[NBINS];          // zero-init
__device__ unsigned g_ncand;                // zero-init
__device__ unsigned g_bar1, g_bar2, g_bar3; // zero-init
__device__ unsigned long long g_cand[CAP];

// order-preserving float <-> uint32 encoding
__device__ __forceinline__ unsigned fenc(float f) {
    unsigned u = __float_as_uint(f);
    return (u & 0x80000000u) ? ~u : (u | 0x80000000u);
}
__device__ __forceinline__ float fdec(unsigned k) {
    unsigned u = (k & 0x80000000u) ? (k & 0x7FFFFFFFu) : ~k;
    return __uint_as_float(u);
}

__device__ __forceinline__ const float* lvlptr(int gi,
                                               const float* g0, const float* g1,
                                               const float* g2,
                                               int& H, int& arow, int& local) {
    if (gi < N0)           { H = 48;  arow = 2; local = gi;            return g0 + (size_t)local * 85; }
    else if (gi < N0 + N1) { H = 96;  arow = 1; local = gi - N0;       return g1 + (size_t)local * 85; }
    else                   { H = 192; arow = 0; local = gi - N0 - N1;  return g2 + (size_t)local * 85; }
}

// grid barrier: atomic arrive, volatile-poll wait
__device__ __forceinline__ void gsync(unsigned* ctr) {
    __syncthreads();
    if (threadIdx.x == 0) {
        __threadfence();
        atomicAdd(ctr, 1u);
        while (*(volatile unsigned*)ctr < FB) __nanosleep(32);
    }
    __syncthreads();
}

// register compare-exchange step for bitonic (j <= 16, via shuffle)
__device__ __forceinline__ unsigned long long cas_reg(unsigned long long v,
                                                      unsigned i, unsigned j,
                                                      unsigned k) {
    unsigned long long pv = __shfl_xor_sync(0xffffffffu, v, j);
    bool lower = (i & j) == 0u;
    bool desc  = (i & k) == 0u;
    unsigned long long mx = v > pv ? v : pv;
    unsigned long long mn = v > pv ? pv : v;
    return (lower == desc) ? mx : mn;
}

// =================== the whole pipeline in one kernel ===================
__global__ void __launch_bounds__(1024) k_all(const float* __restrict__ g0,
                                              const float* __restrict__ g1,
                                              const float* __restrict__ g2,
                                              const float* __restrict__ anch,
                                              float* __restrict__ out) {
    __shared__ __align__(16) char smem_raw[36864];   // 36 KB union
    __shared__ float s_conf[1024];
    const int t    = threadIdx.x;
    const int b    = blockIdx.x;
    const int lane = t & 31;
    const int w    = t >> 5;
    const int gi0  = b * 1024 + t;
    const bool own = gi0 < N_TOTAL;

    // ---------------- phase 0: decode (warp w -> boxes base..base+31) -----
    const int base = b * 1024 + w * 32;
    float wmax = -3.4e38f, wmin = 3.4e38f;

    float v0 = 0.f, v1 = 0.f, v2 = -3.4e38f;
    if (base < N_TOTAL) {
        int H, arow, local;
        const float* p = lvlptr(base, g0, g1, g2, H, arow, local);
        v0 = p[lane];
        v1 = p[32 + lane];
        v2 = (lane < 21) ? p[64 + lane] : -3.4e38f;
    }

    for (int k = 0; k < 32; k++) {
        const int gi = base + k;
        // prefetch next box
        float n0 = 0.f, n1 = 0.f, n2 = -3.4e38f;
        if (k < 31 && gi + 1 < N_TOTAL) {
            int H, arow, local;
            const float* p = lvlptr(gi + 1, g0, g1, g2, H, arow, local);
            n0 = p[lane];
            n1 = p[32 + lane];
            n2 = (lane < 21) ? p[64 + lane] : -3.4e38f;
        }

        if (gi < N_TOTAL) {
            // per-lane class argmax candidates (ties -> lowest class)
            float bv = -3.4e38f; int bc = 0x7FFFFFFF;
            if (lane >= 5)            { bv = v0; bc = lane - 5; }
            if (v1 > bv)              { bv = v1; bc = 27 + lane; }
            if (lane < 21 && v2 > bv) { bv = v2; bc = 59 + lane; }

            #pragma unroll
            for (int o = 16; o; o >>= 1) {
                float ov = __shfl_xor_sync(0xffffffffu, bv, o);
                int   oc = __shfl_xor_sync(0xffffffffu, bc, o);
                if (ov > bv || (ov == bv && oc < bc)) { bv = ov; bc = oc; }
            }
            wmax = fmaxf(wmax, bv);
            wmin = fminf(wmin, bv);

            float tx  = __shfl_sync(0xffffffffu, v0, 0);
            float ty  = __shfl_sync(0xffffffffu, v0, 1);
            float tw  = __shfl_sync(0xffffffffu, v0, 2);
            float th  = __shfl_sync(0xffffffffu, v0, 3);
            float obj = __shfl_sync(0xffffffffu, v0, 4);

            if (lane == 0) {
                int H, arow, local;
                lvlptr(gi, g0, g1, g2, H, arow, local);
                int a    = local % 3;
                int cell = local / 3;
                int cx   = cell % H;   // W == H for all levels
                int cy   = cell / H;

                float fH = (float)H;
                float fx = (tx + (float)cx) / fH;
                float fy = (ty + (float)cy) / fH;

                float ax = anch[arow * 6 + a * 2 + 0];
                float ay = anch[arow * 6 + a * 2 + 1];
                float bw = expf(tw) * ax;
                float bh = expf(th) * ay;

                g_box[gi] = make_float4(fx - bw * 0.5f, fy - bh * 0.5f,
                                        fx + bw * 0.5f, fy + bh * 0.5f);
                g_cls[gi] = (float)bc;
                s_conf[w * 32 + k] = obj;
            }
        }
        v0 = n0; v1 = n1; v2 = n2;
    }

    // ---- block reduce maxprob max/min -> global atomics ----
    #pragma unroll
    for (int o = 16; o; o >>= 1) {
        wmax = fmaxf(wmax, __shfl_xor_sync(0xffffffffu, wmax, o));
        wmin = fminf(wmin, __shfl_xor_sync(0xffffffffu, wmin, o));
    }
    float* s_mx = (float*)smem_raw;
    float* s_mn = (float*)smem_raw + 32;
    if (lane == 0) { s_mx[w] = wmax; s_mn[w] = wmin; }
    __syncthreads();
    if (t == 0) {
        float mx = s_mx[0], mn = s_mn[0];
        #pragma unroll
        for (int k = 1; k < 32; k++) {
            mx = fmaxf(mx, s_mx[k]);
            mn = fminf(mn, s_mn[k]);
        }
        atomicMax(&g_encmax, fenc(mx));
        atomicMin(&g_encmin, fenc(mn));
    }
    __syncthreads();   // t0 done reading s_mx/s_mn before smem reuse

    // ---- zero smem hist, then wait for all blocks (encmax/min final) ----
    unsigned* sh = (unsigned*)smem_raw;   // 16 KB
    #pragma unroll
    for (int k = 0; k < 4; k++) sh[t + k * 1024] = 0u;
    gsync(&g_bar1);

    // ---------------- phase 1: score + histogram ----------------
    const float Mx = fdec(__ldcg(&g_encmax));
    const float Mn = fdec(__ldcg(&g_encmin));
    unsigned e = 0u;
    if (own) {
        float c = s_conf[t];
        e = fenc(fmaxf(c * Mx, c * Mn));
        atomicAdd(&sh[e >> BIN_SHIFT], 1u);
    }
    __syncthreads();
    #pragma unroll
    for (int k = 0; k < 4; k++) {
        unsigned v = sh[t + k * 1024];
        if (v) atomicAdd(&g_hist[t + k * 1024], v);
    }
    gsync(&g_bar2);

    // ---------------- phase 2: threshold (every block, locally) ----------
    unsigned* ss = (unsigned*)smem_raw;   // reuse (4 KB)
    __shared__ unsigned s_thresh;
    unsigned c0 = __ldcg(&g_hist[POSBIN0 + 2 * t]);
    unsigned c1 = __ldcg(&g_hist[POSBIN0 + 2 * t + 1]);
    if (t == 0) s_thresh = POSBIN0;       // default: all positives qualify
    ss[t] = c0 + c1;
    __syncthreads();
    for (int off = 1; off < 1024; off <<= 1) {
        unsigned v = (t + off < 1024) ? ss[t + off] : 0u;
        __syncthreads();
        ss[t] += v;
        __syncthreads();
    }
    unsigned sufInc   = ss[t];
    unsigned sufAfter = (t < 1023) ? ss[t + 1] : 0u;
    if (sufAfter < TARGET && sufInc >= TARGET) {
        s_thresh = (sufAfter + c1 >= TARGET) ? (POSBIN0 + 2 * t + 1)
                                             : (POSBIN0 + 2 * t);
    }
    __syncthreads();
    const unsigned threshB = s_thresh;

    // ---------------- phase 3: compact ----------------
    if (own && (e >> BIN_SHIFT) >= threshB) {
        unsigned pos = atomicAdd(&g_ncand, 1u);
        if (pos < CAP)
            g_cand[pos] = ((unsigned long long)e << 32) |
                          (unsigned long long)(0xFFFFFFFFu - (unsigned)gi0);
    }

    // ---- barrier 3: arrive-only; block 0 waits ----
    __syncthreads();
    if (t == 0) {
        __threadfence();
        atomicAdd(&g_bar3, 1u);
    }
    if (b != 0) return;
    if (t == 0) {
        while (*(volatile unsigned*)&g_bar3 < FB) __nanosleep(32);
    }
    __syncthreads();

    // ---------------- phase 4 (block 0): hybrid bitonic sort --------------
    unsigned long long* keys = (unsigned long long*)smem_raw;      // 16 KB
    float4* sbox = (float4*)(smem_raw + 16384);                    // 16 KB
    float*  scls = (float*)(smem_raw + 32768);                     // 4 KB

    const unsigned M = min(__ldcg(&g_ncand), (unsigned)CAP);
    unsigned long long a = (t        < (int)M) ? __ldcg(&g_cand[t])        : 0ull;
    unsigned long long bk = (t + 1024 < (int)M) ? __ldcg(&g_cand[t + 1024]) : 0ull;

    #pragma unroll
    for (unsigned k = 2; k <= 32; k <<= 1) {
        #pragma unroll
        for (unsigned j = k >> 1; j > 0; j >>= 1) {
            a  = cas_reg(a,  (unsigned)t,          j, k);
            bk = cas_reg(bk, (unsigned)t + 1024u,  j, k);
        }
    }
    keys[t] = a; keys[t + 1024] = bk;
    __syncthreads();

    for (unsigned k = 64; k <= CAP; k <<= 1) {
        for (unsigned j = k >> 1; j >= 32; j >>= 1) {
            #pragma unroll
            for (unsigned bb = 0; bb < 2; bb++) {
                unsigned i = (unsigned)t + bb * 1024u;
                unsigned ixj = i ^ j;
                if (ixj > i) {
                    unsigned long long x = keys[i], y = keys[ixj];
                    bool desc = ((i & k) == 0u);
                    if ((x < y) == desc) { keys[i] = y; keys[ixj] = x; }
                }
            }
            __syncthreads();
        }
        a = keys[t]; bk = keys[t + 1024];
        #pragma unroll
        for (unsigned j = 16; j > 0; j >>= 1) {
            a  = cas_reg(a,  (unsigned)t,         j, k);
            bk = cas_reg(bk, (unsigned)t + 1024u, j, k);
        }
        keys[t] = a; keys[t + 1024] = bk;
        __syncthreads();
    }

    // ---------------- phase 5: prefetch top PRE boxes; zero output -------
    if (t < PRE && t < (int)M) {
        unsigned idx = 0xFFFFFFFFu - (unsigned)(keys[t] & 0xFFFFFFFFull);
        float4 bx;
        bx.x = __ldcg(&g_box[idx].x);
        bx.y = __ldcg(&g_box[idx].y);
        bx.z = __ldcg(&g_box[idx].z);
        bx.w = __ldcg(&g_box[idx].w);
        sbox[t] = bx;
        scls[t] = __ldcg(&g_cls[idx]);
    }
    if (t < 601) out[t] = 0.0f;
    __syncthreads();

    // ---------------- phase 6: warp 0 greedy scan -------------------------
    if (t < 32) {
        float kx1[4], ky1[4], kx2[4], ky2[4], ka[4];
        int kept = 0;

        for (unsigned r = 0; r < M && kept < MAX_BOXES; r++) {
            unsigned long long key = keys[r];
            unsigned senc = (unsigned)(key >> 32);
            if (senc <= 0x80000000u) break;       // best remaining score <= 0

            float4 c;
            float cls;
            if (r < PRE) { c = sbox[r]; cls = scls[r]; }
            else {
                unsigned idx = 0xFFFFFFFFu - (unsigned)(key & 0xFFFFFFFFull);
                c.x = __ldcg(&g_box[idx].x);
                c.y = __ldcg(&g_box[idx].y);
                c.z = __ldcg(&g_box[idx].z);
                c.w = __ldcg(&g_box[idx].w);
                cls = __ldcg(&g_cls[idx]);
            }
            float carea = (c.z - c.x) * (c.w - c.y);

            bool conflict = false;
            #pragma unroll
            for (int q = 0; q < 4; q++) {
                if (q * 32 + lane < kept) {
                    float iw = fmaxf(fminf(kx2[q], c.z) - fmaxf(kx1[q], c.x), 0.0f);
                    float ih = fmaxf(fminf(ky2[q], c.w) - fmaxf(ky1[q], c.y), 0.0f);
                    float inter = iw * ih;
                    float iou = inter / (carea + ka[q] - inter);
                    conflict |= (iou > 0.5f);
                }
            }
            if (__ballot_sync(0xffffffffu, conflict) == 0u) {
                int s = kept;
                #pragma unroll
                for (int q = 0; q < 4; q++) {
                    if ((s >> 5) == q && lane == (s & 31)) {
                        kx1[q] = c.x; ky1[q] = c.y;
                        kx2[q] = c.z; ky2[q] = c.w;
                        ka[q]  = carea;
                    }
                }
                if (lane == 0) {
                    out[s * 4 + 0] = c.x;
                    out[s * 4 + 1] = c.y;
                    out[s * 4 + 2] = c.z;
                    out[s * 4 + 3] = c.w;
                    out[400 + s]   = fdec(senc);
                    out[500 + s]   = cls;
                }
                kept++;
            }
        }
        if (lane == 0) out[600] = (float)kept;
    }

    // ---------------- phase 7: reset state for next call ------------------
    __syncthreads();
    #pragma unroll
    for (int k = 0; k < 4; k++) g_hist[t + k * 1024] = 0u;
    if (t == 0) {
        g_ncand  = 0u;
        g_bar1   = 0u;
        g_bar2   = 0u;
        g_bar3   = 0u;
        g_encmax = 0u;
        g_encmin = 0xFFFFFFFFu;
    }
}

extern "C" void kernel_launch(void* const* d_in, const int* in_sizes, int n_in,
                              void* d_out, int out_size) {
    const float* g0   = (const float*)d_in[0];
    const float* g1   = (const float*)d_in[1];
    const float* g2   = (const float*)d_in[2];
    const float* anch = (const float*)d_in[3];
    float* out = (float*)d_out;

    k_all<<<FB, 1024>>>(g0, g1, g2, anch, out);
}

// round 6
// speedup vs baseline: 4.3992x; 1.2159x over previous
#include <cuda_runtime.h>
#include <cstdint>

#define N0 6912      // 48*48*3
#define N1 27648     // 96*96*3
#define N2 110592    // 192*192*3
#define N_TOTAL 145152
#define MAX_BOXES 100

#define NBINS 4096
#define BIN_SHIFT 20
#define POSBIN0 2048          // bin of enc(+0.0)
#define CAP 2048
#define PRE 1024
#define TARGET 1024
#define FB 142                // blocks (142*1024 = 145408 >= N_TOTAL)

// ---------------- scratch (device globals; zero/const static init) -------
__device__ float4 g_box[N_TOTAL];           // written only for candidates
__device__ float  g_cls[N_TOTAL];           // written only for candidates
__device__ unsigned g_encmax = 0u;
__device__ unsigned g_encmin = 0xFFFFFFFFu;
__device__ unsigned g_hist[NBINS];          // zero-init
__device__ unsigned g_ncand;                // zero-init
__device__ unsigned g_bar1, g_bar2, g_bar3; // zero-init
__device__ unsigned long long g_cand[CAP];

// order-preserving float <-> uint32 encoding
__device__ __forceinline__ unsigned fenc(float f) {
    unsigned u = __float_as_uint(f);
    return (u & 0x80000000u) ? ~u : (u | 0x80000000u);
}
__device__ __forceinline__ float fdec(unsigned k) {
    unsigned u = (k & 0x80000000u) ? (k & 0x7FFFFFFFu) : ~k;
    return __uint_as_float(u);
}

__device__ __forceinline__ const float* lvlptr(int gi,
                                               const float* g0, const float* g1,
                                               const float* g2,
                                               int& H, int& arow, int& local) {
    if (gi < N0)           { H = 48;  arow = 2; local = gi;            return g0 + (size_t)local * 85; }
    else if (gi < N0 + N1) { H = 96;  arow = 1; local = gi - N0;       return g1 + (size_t)local * 85; }
    else                   { H = 192; arow = 0; local = gi - N0 - N1;  return g2 + (size_t)local * 85; }
}

// grid barrier: atomic arrive, volatile-poll wait
__device__ __forceinline__ void gsync(unsigned* ctr) {
    __threadfence();
    __syncthreads();
    if (threadIdx.x == 0) {
        atomicAdd(ctr, 1u);
        while (*(volatile unsigned*)ctr < FB) __nanosleep(32);
    }
    __syncthreads();
}

// register compare-exchange step for bitonic (j <= 16, via shuffle)
__device__ __forceinline__ unsigned long long cas_reg(unsigned long long v,
                                                      unsigned i, unsigned j,
                                                      unsigned k) {
    unsigned long long pv = __shfl_xor_sync(0xffffffffu, v, j);
    bool lower = (i & j) == 0u;
    bool desc  = (i & k) == 0u;
    unsigned long long mx = v > pv ? v : pv;
    unsigned long long mn = v > pv ? pv : v;
    return (lower == desc) ? mx : mn;
}

// =================== the whole pipeline in one kernel ===================
__global__ void __launch_bounds__(1024) k_all(const float* __restrict__ g0,
                                              const float* __restrict__ g1,
                                              const float* __restrict__ g2,
                                              const float* __restrict__ anch,
                                              float* __restrict__ out) {
    __shared__ __align__(16) char smem_raw[36864];   // 36 KB union
    __shared__ float s_conf[1024];
    __shared__ unsigned s_thresh;
    const int t    = threadIdx.x;
    const int b    = blockIdx.x;
    const int lane = t & 31;
    const int w    = t >> 5;
    const int gi0  = b * 1024 + t;
    const bool own = gi0 < N_TOTAL;

    // ---------------- phase A: per-box maxprob (value only) + conf --------
    // warp w owns boxes base..base+31; N_TOTAL % 32 == 0, so a warp is
    // either fully valid or fully invalid.
    const int base = b * 1024 + w * 32;
    unsigned wemax = 0u, wemin = 0xFFFFFFFFu;

    if (base < N_TOTAL) {
        int H, arow, local;
        const float* p = lvlptr(base, g0, g1, g2, H, arow, local);
        float v0 = p[lane];
        float v1 = p[32 + lane];
        float v2 = (lane < 21) ? p[64 + lane] : -3.4e38f;

        #pragma unroll 4
        for (int k = 0; k < 32; k++) {
            // prefetch next box
            float n0 = 0.f, n1 = -3.4e38f, n2 = -3.4e38f;
            if (k < 31) {
                const float* pn = lvlptr(base + k + 1, g0, g1, g2, H, arow, local);
                n0 = pn[lane];
                n1 = pn[32 + lane];
                n2 = (lane < 21) ? pn[64 + lane] : -3.4e38f;
            }

            float bv = (lane >= 5) ? v0 : -3.4e38f;   // v0 lanes 5..31 = cp[0..26]
            bv = fmaxf(bv, v1);                       // cp[27..58]
            bv = fmaxf(bv, v2);                       // cp[59..79] (else -inf)
            unsigned ebv = __reduce_max_sync(0xffffffffu, fenc(bv));
            wemax = max(wemax, ebv);
            wemin = min(wemin, ebv);
            if (lane == 4) s_conf[w * 32 + k] = v0;   // obj

            v0 = n0; v1 = n1; v2 = n2;
        }
    }

    // block reduce -> global atomics (wemax/wemin warp-uniform)
    unsigned* s_mx = (unsigned*)smem_raw;
    unsigned* s_mn = (unsigned*)smem_raw + 32;
    if (lane == 0) { s_mx[w] = wemax; s_mn[w] = wemin; }
    __syncthreads();
    if (t == 0) {
        unsigned mx = s_mx[0], mn = s_mn[0];
        #pragma unroll
        for (int k = 1; k < 32; k++) {
            mx = max(mx, s_mx[k]);
            mn = min(mn, s_mn[k]);
        }
        atomicMax(&g_encmax, mx);
        atomicMin(&g_encmin, mn);
    }
    __syncthreads();

    // zero smem hist, wait for all blocks (encmax/min final)
    unsigned* sh = (unsigned*)smem_raw;   // 16 KB
    #pragma unroll
    for (int k = 0; k < 4; k++) sh[t + k * 1024] = 0u;
    gsync(&g_bar1);

    // ---------------- phase B: score + histogram ----------------
    const float Mx = fdec(__ldcg(&g_encmax));
    const float Mn = fdec(__ldcg(&g_encmin));
    unsigned e = 0u;
    if (own) {
        float c = s_conf[t];
        e = fenc(fmaxf(c * Mx, c * Mn));
        atomicAdd(&sh[e >> BIN_SHIFT], 1u);
    }
    __syncthreads();
    #pragma unroll
    for (int k = 0; k < 4; k++) {
        unsigned v = sh[t + k * 1024];
        if (v) atomicAdd(&g_hist[t + k * 1024], v);
    }
    gsync(&g_bar2);

    // ---------------- phase C: threshold (every block, locally) ----------
    unsigned* ss = (unsigned*)smem_raw;   // reuse (4 KB)
    unsigned c0 = __ldcg(&g_hist[POSBIN0 + 2 * t]);
    unsigned c1 = __ldcg(&g_hist[POSBIN0 + 2 * t + 1]);
    if (t == 0) s_thresh = POSBIN0;       // default: all positives qualify
    ss[t] = c0 + c1;
    __syncthreads();
    for (int off = 1; off < 1024; off <<= 1) {
        unsigned v = (t + off < 1024) ? ss[t + off] : 0u;
        __syncthreads();
        ss[t] += v;
        __syncthreads();
    }
    unsigned sufInc   = ss[t];
    unsigned sufAfter = (t < 1023) ? ss[t + 1] : 0u;
    if (sufAfter < TARGET && sufInc >= TARGET) {
        s_thresh = (sufAfter + c1 >= TARGET) ? (POSBIN0 + 2 * t + 1)
                                             : (POSBIN0 + 2 * t);
    }
    __syncthreads();
    const unsigned threshB = s_thresh;

    // ---------------- phase D: compact + candidate-only decode -----------
    if (own && (e >> BIN_SHIFT) >= threshB) {
        unsigned pos = atomicAdd(&g_ncand, 1u);
        if (pos < CAP) {
            g_cand[pos] = ((unsigned long long)e << 32) |
                          (unsigned long long)(0xFFFFFFFFu - (unsigned)gi0);

            // full decode for this candidate only (L2-hot reload)
            int H, arow, local;
            const float* p = lvlptr(gi0, g0, g1, g2, H, arow, local);
            float tx = p[0], ty = p[1], tw = p[2], th = p[3];
            float best = p[5];
            int bc = 0;
            #pragma unroll 8
            for (int c = 1; c < 80; c++) {
                float vv = p[5 + c];
                if (vv > best) { best = vv; bc = c; }
            }

            int a    = local % 3;
            int cell = local / 3;
            int cx   = cell % H;   // W == H for all levels
            int cy   = cell / H;
            float fH = (float)H;
            float fx = (tx + (float)cx) / fH;
            float fy = (ty + (float)cy) / fH;
            float ax = anch[arow * 6 + a * 2 + 0];
            float ay = anch[arow * 6 + a * 2 + 1];
            float bw = expf(tw) * ax;
            float bh = expf(th) * ay;

            g_box[gi0] = make_float4(fx - bw * 0.5f, fy - bh * 0.5f,
                                     fx + bw * 0.5f, fy + bh * 0.5f);
            g_cls[gi0] = (float)bc;
        }
    }

    // barrier 3: arrive-only; block 0 waits
    __threadfence();
    __syncthreads();
    if (t == 0) atomicAdd(&g_bar3, 1u);
    if (b != 0) return;
    if (t == 0) {
        while (*(volatile unsigned*)&g_bar3 < FB) __nanosleep(32);
    }
    __syncthreads();

    // ---------------- phase E (block 0): hybrid bitonic sort --------------
    unsigned long long* keys = (unsigned long long*)smem_raw;      // 16 KB
    float4* sbox = (float4*)(smem_raw + 16384);                    // 16 KB
    float*  scls = (float*)(smem_raw + 32768);                     // 4 KB

    const unsigned M = min(__ldcg(&g_ncand), (unsigned)CAP);
    unsigned long long a  = (t        < (int)M) ? __ldcg(&g_cand[t])        : 0ull;
    unsigned long long bk = (t + 1024 < (int)M) ? __ldcg(&g_cand[t + 1024]) : 0ull;

    #pragma unroll
    for (unsigned k = 2; k <= 32; k <<= 1) {
        #pragma unroll
        for (unsigned j = k >> 1; j > 0; j >>= 1) {
            a  = cas_reg(a,  (unsigned)t,         j, k);
            bk = cas_reg(bk, (unsigned)t + 1024u, j, k);
        }
    }
    keys[t] = a; keys[t + 1024] = bk;
    __syncthreads();

    for (unsigned k = 64; k <= CAP; k <<= 1) {
        for (unsigned j = k >> 1; j >= 32; j >>= 1) {
            #pragma unroll
            for (unsigned bb = 0; bb < 2; bb++) {
                unsigned i = (unsigned)t + bb * 1024u;
                unsigned ixj = i ^ j;
                if (ixj > i) {
                    unsigned long long x = keys[i], y = keys[ixj];
                    bool desc = ((i & k) == 0u);
                    if ((x < y) == desc) { keys[i] = y; keys[ixj] = x; }
                }
            }
            __syncthreads();
        }
        a = keys[t]; bk = keys[t + 1024];
        #pragma unroll
        for (unsigned j = 16; j > 0; j >>= 1) {
            a  = cas_reg(a,  (unsigned)t,         j, k);
            bk = cas_reg(bk, (unsigned)t + 1024u, j, k);
        }
        keys[t] = a; keys[t + 1024] = bk;
        __syncthreads();
    }

    // ---------------- phase F: prefetch top PRE boxes; zero output -------
    if (t < PRE && t < (int)M) {
        unsigned idx = 0xFFFFFFFFu - (unsigned)(keys[t] & 0xFFFFFFFFull);
        float4 bx;
        bx.x = __ldcg(&g_box[idx].x);
        bx.y = __ldcg(&g_box[idx].y);
        bx.z = __ldcg(&g_box[idx].z);
        bx.w = __ldcg(&g_box[idx].w);
        sbox[t] = bx;
        scls[t] = __ldcg(&g_cls[idx]);
    }
    if (t < 601) out[t] = 0.0f;
    __syncthreads();

    // ---------------- phase G: warp 0 greedy scan -------------------------
    if (t < 32) {
        float kx1[4], ky1[4], kx2[4], ky2[4], ka[4];
        int kept = 0;

        for (unsigned r = 0; r < M && kept < MAX_BOXES; r++) {
            unsigned long long key = keys[r];
            unsigned senc = (unsigned)(key >> 32);
            if (senc <= 0x80000000u) break;       // best remaining score <= 0

            float4 c;
            float cls;
            if (r < PRE) { c = sbox[r]; cls = scls[r]; }
            else {
                unsigned idx = 0xFFFFFFFFu - (unsigned)(key & 0xFFFFFFFFull);
                c.x = __ldcg(&g_box[idx].x);
                c.y = __ldcg(&g_box[idx].y);
                c.z = __ldcg(&g_box[idx].z);
                c.w = __ldcg(&g_box[idx].w);
                cls = __ldcg(&g_cls[idx]);
            }
            float carea = (c.z - c.x) * (c.w - c.y);

            bool conflict = false;
            #pragma unroll
            for (int q = 0; q < 4; q++) {
                if (q * 32 + lane < kept) {
                    float iw = fmaxf(fminf(kx2[q], c.z) - fmaxf(kx1[q], c.x), 0.0f);
                    float ih = fmaxf(fminf(ky2[q], c.w) - fmaxf(ky1[q], c.y), 0.0f);
                    float inter = iw * ih;
                    float iou = inter / (carea + ka[q] - inter);
                    conflict |= (iou > 0.5f);
                }
            }
            if (__ballot_sync(0xffffffffu, conflict) == 0u) {
                int s = kept;
                #pragma unroll
                for (int q = 0; q < 4; q++) {
                    if ((s >> 5) == q && lane == (s & 31)) {
                        kx1[q] = c.x; ky1[q] = c.y;
                        kx2[q] = c.z; ky2[q] = c.w;
                        ka[q]  = carea;
                    }
                }
                if (lane == 0) {
                    out[s * 4 + 0] = c.x;
                    out[s * 4 + 1] = c.y;
                    out[s * 4 + 2] = c.z;
                    out[s * 4 + 3] = c.w;
                    out[400 + s]   = fdec(senc);
                    out[500 + s]   = cls;
                }
                kept++;
            }
        }
        if (lane == 0) out[600] = (float)kept;
    }

    // ---------------- phase H: reset state for next call ------------------
    __syncthreads();
    #pragma unroll
    for (int k = 0; k < 4; k++) g_hist[t + k * 1024] = 0u;
    if (t == 0) {
        g_ncand  = 0u;
        g_bar1   = 0u;
        g_bar2   = 0u;
        g_bar3   = 0u;
        g_encmax = 0u;
        g_encmin = 0xFFFFFFFFu;
    }
}

extern "C" void kernel_launch(void* const* d_in, const int* in_sizes, int n_in,
                              void* d_out, int out_size) {
    const float* g0   = (const float*)d_in[0];
    const float* g1   = (const float*)d_in[1];
    const float* g2   = (const float*)d_in[2];
    const float* anch = (const float*)d_in[3];
    float* out = (float*)d_out;

    k_all<<<FB, 1024>>>(g0, g1, g2, anch, out);
}

// round 7
// speedup vs baseline: 4.5683x; 1.0384x over previous
#include <cuda_runtime.h>
#include <cstdint>

#define N0 6912      // 48*48*3
#define N1 27648     // 96*96*3
#define N2 110592    // 192*192*3
#define N_TOTAL 145152
#define MAX_BOXES 100

#define NBINS 4096
#define BIN_SHIFT 20
#define POSBIN0 2048          // bin of enc(+0.0)
#define CAP 2048
#define PRE 1024
#define TARGET 1024
#define FB 142                // blocks (142*1024 = 145408 >= N_TOTAL)

// ---------------- scratch (device globals; zero/const static init) -------
__device__ float4 g_box[N_TOTAL];           // written only for candidates
__device__ float  g_cls[N_TOTAL];           // written only for candidates
__device__ unsigned g_encmax = 0u;
__device__ unsigned g_encmin = 0xFFFFFFFFu;
__device__ unsigned g_hist[NBINS];          // zero-init
__device__ unsigned g_ncand;                // zero-init
__device__ unsigned g_bar1, g_bar2, g_bar3; // zero-init
__device__ unsigned long long g_cand[CAP];

// order-preserving float <-> uint32 encoding
__device__ __forceinline__ unsigned fenc(float f) {
    unsigned u = __float_as_uint(f);
    return (u & 0x80000000u) ? ~u : (u | 0x80000000u);
}
__device__ __forceinline__ float fdec(unsigned k) {
    unsigned u = (k & 0x80000000u) ? (k & 0x7FFFFFFFu) : ~k;
    return __uint_as_float(u);
}

__device__ __forceinline__ const float* lvlptr(int gi,
                                               const float* g0, const float* g1,
                                               const float* g2,
                                               int& H, int& arow, int& local) {
    if (gi < N0)           { H = 48;  arow = 2; local = gi;            return g0 + (size_t)local * 85; }
    else if (gi < N0 + N1) { H = 96;  arow = 1; local = gi - N0;       return g1 + (size_t)local * 85; }
    else                   { H = 192; arow = 0; local = gi - N0 - N1;  return g2 + (size_t)local * 85; }
}

// grid barrier: atomic arrive, volatile-poll wait
__device__ __forceinline__ void gsync(unsigned* ctr) {
    __threadfence();
    __syncthreads();
    if (threadIdx.x == 0) {
        atomicAdd(ctr, 1u);
        while (*(volatile unsigned*)ctr < FB) __nanosleep(32);
    }
    __syncthreads();
}

// register compare-exchange step for bitonic (j <= 16, via shuffle)
__device__ __forceinline__ unsigned long long cas_reg(unsigned long long v,
                                                      unsigned i, unsigned j,
                                                      unsigned k) {
    unsigned long long pv = __shfl_xor_sync(0xffffffffu, v, j);
    bool lower = (i & j) == 0u;
    bool desc  = (i & k) == 0u;
    unsigned long long mx = v > pv ? v : pv;
    unsigned long long mn = v > pv ? pv : v;
    return (lower == desc) ? mx : mn;
}

// =================== the whole pipeline in one kernel ===================
__global__ void __launch_bounds__(1024) k_all(const float* __restrict__ g0,
                                              const float* __restrict__ g1,
                                              const float* __restrict__ g2,
                                              const float* __restrict__ anch,
                                              float* __restrict__ out) {
    __shared__ __align__(16) char smem_raw[36864];   // 36 KB union
    __shared__ float s_conf[1024];
    __shared__ unsigned s_thresh;
    __shared__ unsigned s_part[32];
    const int t    = threadIdx.x;
    const int b    = blockIdx.x;
    const int lane = t & 31;
    const int w    = t >> 5;
    const int gi0  = b * 1024 + t;
    const bool own = gi0 < N_TOTAL;

    // ---------------- phase A: per-box maxprob (value only) + conf --------
    // warp w owns boxes base..base+31. Level boundaries (6912, 34560) are
    // multiples of 32, so all 32 boxes of a warp live in ONE level.
    const int base = b * 1024 + w * 32;
    unsigned wemax = 0u, wemin = 0xFFFFFFFFu;

    if (base < N_TOTAL) {
        int H, arow, local;
        const float* p = lvlptr(base, g0, g1, g2, H, arow, local);

        #pragma unroll
        for (int kb = 0; kb < 32; kb += 8) {
            float a0[8], a1[8], a2[8];
            // issue all 24 loads for 8 boxes (deep MLP)
            #pragma unroll
            for (int k = 0; k < 8; k++) {
                const float* q = p + (size_t)(kb + k) * 85;
                a0[k] = q[lane];
                a1[k] = q[32 + lane];
                a2[k] = (lane < 21) ? q[64 + lane] : -3.4e38f;
            }
            // then consume
            #pragma unroll
            for (int k = 0; k < 8; k++) {
                float bv = (lane >= 5) ? a0[k] : -3.4e38f;   // cp[0..26]
                bv = fmaxf(bv, a1[k]);                       // cp[27..58]
                bv = fmaxf(bv, a2[k]);                       // cp[59..79]
                unsigned ebv = __reduce_max_sync(0xffffffffu, fenc(bv));
                wemax = max(wemax, ebv);
                wemin = min(wemin, ebv);
                if (lane == 4) s_conf[w * 32 + kb + k] = a0[k];  // obj
            }
        }
    }

    // block reduce -> global atomics (wemax/wemin warp-uniform)
    unsigned* s_mx = (unsigned*)smem_raw;
    unsigned* s_mn = (unsigned*)smem_raw + 32;
    if (lane == 0) { s_mx[w] = wemax; s_mn[w] = wemin; }
    __syncthreads();
    if (t == 0) {
        unsigned mx = s_mx[0], mn = s_mn[0];
        #pragma unroll
        for (int k = 1; k < 32; k++) {
            mx = max(mx, s_mx[k]);
            mn = min(mn, s_mn[k]);
        }
        atomicMax(&g_encmax, mx);
        atomicMin(&g_encmin, mn);
    }
    __syncthreads();

    // zero smem hist, wait for all blocks (encmax/min final)
    unsigned* sh = (unsigned*)smem_raw;   // 16 KB
    #pragma unroll
    for (int k = 0; k < 4; k++) sh[t + k * 1024] = 0u;
    gsync(&g_bar1);

    // ---------------- phase B: score + histogram ----------------
    const float Mx = fdec(__ldcg(&g_encmax));
    const float Mn = fdec(__ldcg(&g_encmin));
    unsigned e = 0u;
    if (own) {
        float c = s_conf[t];
        e = fenc(fmaxf(c * Mx, c * Mn));
        atomicAdd(&sh[e >> BIN_SHIFT], 1u);
    }
    __syncthreads();
    #pragma unroll
    for (int k = 0; k < 4; k++) {
        unsigned v = sh[t + k * 1024];
        if (v) atomicAdd(&g_hist[t + k * 1024], v);
    }
    gsync(&g_bar2);

    // ---------------- phase C: threshold (warp suffix scan) --------------
    {
        unsigned c0 = __ldcg(&g_hist[POSBIN0 + 2 * t]);
        unsigned c1 = __ldcg(&g_hist[POSBIN0 + 2 * t + 1]);
        if (t == 0) s_thresh = POSBIN0;   // default: all positives qualify
        unsigned arr = c0 + c1;

        // inclusive suffix scan within warp (sum over lanes >= lane)
        unsigned s = arr;
        #pragma unroll
        for (int off = 1; off < 32; off <<= 1) {
            unsigned v = __shfl_down_sync(0xffffffffu, s, off);
            if (lane + off < 32) s += v;
        }
        if (lane == 0) s_part[w] = s;     // warp total
        __syncthreads();
        if (w == 0) {
            unsigned pv = s_part[lane];
            unsigned ps = pv;
            #pragma unroll
            for (int off = 1; off < 32; off <<= 1) {
                unsigned v = __shfl_down_sync(0xffffffffu, ps, off);
                if (lane + off < 32) ps += v;
            }
            s_part[lane] = ps - pv;       // exclusive suffix: warps > lane
        }
        __syncthreads();
        unsigned sufInc   = s + s_part[w];
        unsigned sufAfter = sufInc - arr;
        if (sufAfter < TARGET && sufInc >= TARGET) {
            s_thresh = (sufAfter + c1 >= TARGET) ? (POSBIN0 + 2 * t + 1)
                                                 : (POSBIN0 + 2 * t);
        }
    }
    __syncthreads();
    const unsigned threshB = s_thresh;

    // ---------------- phase D: compact + candidate-only decode -----------
    if (own && (e >> BIN_SHIFT) >= threshB) {
        unsigned pos = atomicAdd(&g_ncand, 1u);
        if (pos < CAP) {
            g_cand[pos] = ((unsigned long long)e << 32) |
                          (unsigned long long)(0xFFFFFFFFu - (unsigned)gi0);

            // full decode for this candidate only (L2-hot reload)
            int H, arow, local;
            const float* p = lvlptr(gi0, g0, g1, g2, H, arow, local);
            float tx = p[0], ty = p[1], tw = p[2], th = p[3];
            float best = p[5];
            int bc = 0;
            #pragma unroll 8
            for (int c = 1; c < 80; c++) {
                float vv = p[5 + c];
                if (vv > best) { best = vv; bc = c; }
            }

            int a    = local % 3;
            int cell = local / 3;
            int cx   = cell % H;   // W == H for all levels
            int cy   = cell / H;
            float fH = (float)H;
            float fx = (tx + (float)cx) / fH;
            float fy = (ty + (float)cy) / fH;
            float ax = anch[arow * 6 + a * 2 + 0];
            float ay = anch[arow * 6 + a * 2 + 1];
            float bw = expf(tw) * ax;
            float bh = expf(th) * ay;

            g_box[gi0] = make_float4(fx - bw * 0.5f, fy - bh * 0.5f,
                                     fx + bw * 0.5f, fy + bh * 0.5f);
            g_cls[gi0] = (float)bc;
        }
    }

    // barrier 3: arrive-only; block 0 waits
    __threadfence();
    __syncthreads();
    if (t == 0) atomicAdd(&g_bar3, 1u);
    if (b != 0) return;
    if (t == 0) {
        while (*(volatile unsigned*)&g_bar3 < FB) __nanosleep(32);
    }
    __syncthreads();

    // ---------------- phase E (block 0): hybrid bitonic sort --------------
    unsigned long long* keys = (unsigned long long*)smem_raw;      // 16 KB
    float4* sbox = (float4*)(smem_raw + 16384);                    // 16 KB
    float*  scls = (float*)(smem_raw + 32768);                     // 4 KB

    const unsigned M = min(__ldcg(&g_ncand), (unsigned)CAP);
    unsigned long long a  = (t        < (int)M) ? __ldcg(&g_cand[t])        : 0ull;
    unsigned long long bk = (t + 1024 < (int)M) ? __ldcg(&g_cand[t + 1024]) : 0ull;

    #pragma unroll
    for (unsigned k = 2; k <= 32; k <<= 1) {
        #pragma unroll
        for (unsigned j = k >> 1; j > 0; j >>= 1) {
            a  = cas_reg(a,  (unsigned)t,         j, k);
            bk = cas_reg(bk, (unsigned)t + 1024u, j, k);
        }
    }
    keys[t] = a; keys[t + 1024] = bk;
    __syncthreads();

    for (unsigned k = 64; k <= CAP; k <<= 1) {
        for (unsigned j = k >> 1; j >= 32; j >>= 1) {
            #pragma unroll
            for (unsigned bb = 0; bb < 2; bb++) {
                unsigned i = (unsigned)t + bb * 1024u;
                unsigned ixj = i ^ j;
                if (ixj > i) {
                    unsigned long long x = keys[i], y = keys[ixj];
                    bool desc = ((i & k) == 0u);
                    if ((x < y) == desc) { keys[i] = y; keys[ixj] = x; }
                }
            }
            __syncthreads();
        }
        a = keys[t]; bk = keys[t + 1024];
        #pragma unroll
        for (unsigned j = 16; j > 0; j >>= 1) {
            a  = cas_reg(a,  (unsigned)t,         j, k);
            bk = cas_reg(bk, (unsigned)t + 1024u, j, k);
        }
        keys[t] = a; keys[t + 1024] = bk;
        __syncthreads();
    }

    // ---------------- phase F: prefetch top PRE boxes; zero output -------
    if (t < PRE && t < (int)M) {
        unsigned idx = 0xFFFFFFFFu - (unsigned)(keys[t] & 0xFFFFFFFFull);
        float4 bx;
        bx.x = __ldcg(&g_box[idx].x);
        bx.y = __ldcg(&g_box[idx].y);
        bx.z = __ldcg(&g_box[idx].z);
        bx.w = __ldcg(&g_box[idx].w);
        sbox[t] = bx;
        scls[t] = __ldcg(&g_cls[idx]);
    }
    if (t < 601) out[t] = 0.0f;
    __syncthreads();

    // ---------------- phase G: warp 0 greedy scan -------------------------
    if (t < 32) {
        float kx1[4], ky1[4], kx2[4], ky2[4], ka[4];
        int kept = 0;

        for (unsigned r = 0; r < M && kept < MAX_BOXES; r++) {
            unsigned long long key = keys[r];
            unsigned senc = (unsigned)(key >> 32);
            if (senc <= 0x80000000u) break;       // best remaining score <= 0

            float4 c;
            float cls;
            if (r < PRE) { c = sbox[r]; cls = scls[r]; }
            else {
                unsigned idx = 0xFFFFFFFFu - (unsigned)(key & 0xFFFFFFFFull);
                c.x = __ldcg(&g_box[idx].x);
                c.y = __ldcg(&g_box[idx].y);
                c.z = __ldcg(&g_box[idx].z);
                c.w = __ldcg(&g_box[idx].w);
                cls = __ldcg(&g_cls[idx]);
            }
            float carea = (c.z - c.x) * (c.w - c.y);

            bool conflict = false;
            #pragma unroll
            for (int q = 0; q < 4; q++) {
                if (q * 32 + lane < kept) {
                    float iw = fmaxf(fminf(kx2[q], c.z) - fmaxf(kx1[q], c.x), 0.0f);
                    float ih = fmaxf(fminf(ky2[q], c.w) - fmaxf(ky1[q], c.y), 0.0f);
                    float inter = iw * ih;
                    float iou = inter / (carea + ka[q] - inter);
                    conflict |= (iou > 0.5f);
                }
            }
            if (__ballot_sync(0xffffffffu, conflict) == 0u) {
                int s = kept;
                #pragma unroll
                for (int q = 0; q < 4; q++) {
                    if ((s >> 5) == q && lane == (s & 31)) {
                        kx1[q] = c.x; ky1[q] = c.y;
                        kx2[q] = c.z; ky2[q] = c.w;
                        ka[q]  = carea;
                    }
                }
                if (lane == 0) {
                    out[s * 4 + 0] = c.x;
                    out[s * 4 + 1] = c.y;
                    out[s * 4 + 2] = c.z;
                    out[s * 4 + 3] = c.w;
                    out[400 + s]   = fdec(senc);
                    out[500 + s]   = cls;
                }
                kept++;
            }
        }
        if (lane == 0) out[600] = (float)kept;
    }

    // ---------------- phase H: reset state for next call ------------------
    __syncthreads();
    #pragma unroll
    for (int k = 0; k < 4; k++) g_hist[t + k * 1024] = 0u;
    if (t == 0) {
        g_ncand  = 0u;
        g_bar1   = 0u;
        g_bar2   = 0u;
        g_bar3   = 0u;
        g_encmax = 0u;
        g_encmin = 0xFFFFFFFFu;
    }
}

extern "C" void kernel_launch(void* const* d_in, const int* in_sizes, int n_in,
                              void* d_out, int out_size) {
    const float* g0   = (const float*)d_in[0];
    const float* g1   = (const float*)d_in[1];
    const float* g2   = (const float*)d_in[2];
    const float* anch = (const float*)d_in[3];
    float* out = (float*)d_out;

    k_all<<<FB, 1024>>>(g0, g1, g2, anch, out);
}